// round 16
// baseline (speedup 1.0000x reference)
#include <cuda_runtime.h>
#include <cuda_bf16.h>

constexpr int kB = 4, kS = 2048, kD = 1024, kH = 16, kDK = 64;
constexpr int kKS = 3072;  // split K dimension [hi | lo | hi]
constexpr int kCap = 32;   // shortlist capacity per row

__device__ __forceinline__ unsigned smem_u32(const void* p) {
  unsigned a;
  asm("{ .reg .u64 t; cvta.to.shared.u64 t, %1; cvt.u32.u64 %0, t; }"
      : "=r"(a) : "l"(p));
  return a;
}

// ---------------- mma.sync helpers (sm_80-class PTX) ----------------
__device__ __forceinline__ void cpasync16(unsigned dst, const void* src) {
  asm volatile("cp.async.cg.shared.global [%0], [%1], 16;" :: "r"(dst), "l"(src));
}
__device__ __forceinline__ void ldmx4(unsigned* r, unsigned addr) {
  asm volatile("ldmatrix.sync.aligned.m8n8.x4.shared.b16 {%0,%1,%2,%3}, [%4];"
               : "=r"(r[0]), "=r"(r[1]), "=r"(r[2]), "=r"(r[3]) : "r"(addr));
}
__device__ __forceinline__ void mma_bf16(float* d, const unsigned* a,
                                         unsigned b0, unsigned b1) {
  asm volatile(
      "mma.sync.aligned.m16n8k16.row.col.f32.bf16.bf16.f32 "
      "{%0,%1,%2,%3}, {%4,%5,%6,%7}, {%8,%9}, {%0,%1,%2,%3};"
      : "+f"(d[0]), "+f"(d[1]), "+f"(d[2]), "+f"(d[3])
      : "r"(a[0]), "r"(a[1]), "r"(a[2]), "r"(a[3]), "r"(b0), "r"(b1));
}

// ---------------- scratch ----------------
__device__ __align__(16) float g_q [(size_t)kB * kH * kS * kDK];
__device__ __align__(16) float g_k [(size_t)kB * kH * kS * kDK];
__device__ __align__(16) float g_v [(size_t)kB * kH * kS * kDK];
__device__ __align__(16) __nv_bfloat16 g_qh[(size_t)kB * kH * kS * kDK];  // bf16(0.125*q)
__device__ __align__(16) __nv_bfloat16 g_kh[(size_t)kB * kH * kS * kDK];  // bf16(k)
__device__ __align__(16) __nv_bfloat16 g_xs [(size_t)kB * kS * kKS];
__device__ __align__(16) __nv_bfloat16 g_ws [(size_t)3 * kH * kDK * kKS];
__device__ __align__(16) __nv_bfloat16 g_wos[(size_t)kD * kKS];
__device__ __align__(16) __nv_bfloat16 g_aos[(size_t)kB * kS * kKS];
__device__ int            g_cnt [(size_t)kB * kH * kS];
__device__ float          g_rowmax[(size_t)kB * kH * kS];
__device__ unsigned short g_slot[(size_t)kB * kH * kS * kCap];

__device__ __forceinline__ void split1(float x, unsigned short& h,
                                       unsigned short& l) {
  __nv_bfloat16 hb = __float2bfloat16_rn(x);
  __nv_bfloat16 lb = __float2bfloat16_rn(x - __bfloat162float(hb));
  h = __bfloat16_as_ushort(hb);
  l = __bfloat16_as_ushort(lb);
}

// ---------------- split kernels ----------------
__global__ __launch_bounds__(256) void split_act_kernel(
    const float* __restrict__ src, __nv_bfloat16* __restrict__ dst) {
  const int m = blockIdx.x;
  const int t = threadIdx.x;
  float4 v = *(const float4*)&src[(size_t)m * kD + t * 4];
  unsigned short h[4], l[4];
  split1(v.x, h[0], l[0]); split1(v.y, h[1], l[1]);
  split1(v.z, h[2], l[2]); split1(v.w, h[3], l[3]);
  uint2 hp = make_uint2((unsigned)h[0] | ((unsigned)h[1] << 16),
                        (unsigned)h[2] | ((unsigned)h[3] << 16));
  uint2 lp = make_uint2((unsigned)l[0] | ((unsigned)l[1] << 16),
                        (unsigned)l[2] | ((unsigned)l[3] << 16));
  __nv_bfloat16* base = dst + (size_t)m * kKS;
  *(uint2*)(base + t * 4) = hp;
  *(uint2*)(base + 1024 + t * 4) = lp;
  *(uint2*)(base + 2048 + t * 4) = hp;
}

// merged QKV-weight + Wo split: grid 4096 (0..3071 -> g_ws, 3072.. -> g_wos)
__global__ __launch_bounds__(256) void split_weights_kernel(
    const float* __restrict__ Wq, const float* __restrict__ Wk,
    const float* __restrict__ Wv, const float* __restrict__ Wo) {
  const int ng = blockIdx.x;
  const float* src;
  __nv_bfloat16* dst;
  size_t stride;
  if (ng < 3072) {
    const int mat = ng >> 10;
    const int h = (ng >> 6) & 15;
    const int n = ng & 63;
    const float* W = (mat == 0 ? Wq : (mat == 1 ? Wk : Wv));
    src = W + (size_t)h * kD * kDK + n;
    stride = kDK;
    dst = g_ws + (size_t)ng * kKS;
  } else {
    const int n = ng - 3072;
    src = Wo + n;
    stride = kD;
    dst = g_wos + (size_t)n * kKS;
  }
#pragma unroll
  for (int it = 0; it < 4; ++it) {
    int d = threadIdx.x + it * 256;
    unsigned short hh, ll;
    split1(src[(size_t)d * stride], hh, ll);
    dst[d] = __ushort_as_bfloat16(hh);
    dst[1024 + d] = __ushort_as_bfloat16(hh);
    dst[2048 + d] = __ushort_as_bfloat16(ll);
  }
}

// ---------------------------------------------------------------------------
// HMMA GEMM (R12/R13 proven core). C[128 x 128] = A[128 x 3072] * B^T.
// mode 0: QKV. Also emits bf16 q-hi (x0.125) and k-hi panels for smax.
// mode 1: proj -> d_out.
// ---------------------------------------------------------------------------
__global__ __launch_bounds__(256) void mm_bf16_kernel(
    const __nv_bfloat16* __restrict__ A, const __nv_bfloat16* __restrict__ Bm,
    float* __restrict__ outP, int mode) {
  extern __shared__ char smem[];
  const unsigned sbase = smem_u32(smem);
  const unsigned aA[2] = {sbase, sbase + 16384};
  const unsigned aB[2] = {sbase + 32768, sbase + 49152};

  const int tid = threadIdx.x;
  const int wid = tid >> 5, lane = tid & 31;
  const int m0 = blockIdx.x * 128, n0 = blockIdx.y * 128;
  const int wm = (wid >> 2) * 64, wn = (wid & 3) * 32;
  const __nv_bfloat16* Asrc = A + (size_t)m0 * kKS;
  const __nv_bfloat16* Bsrc = Bm + (size_t)n0 * kKS;

  float acc[4][4][4];
#pragma unroll
  for (int mi = 0; mi < 4; ++mi)
#pragma unroll
    for (int ni = 0; ni < 4; ++ni)
#pragma unroll
      for (int r = 0; r < 4; ++r) acc[mi][ni][r] = 0.f;

#define STAGE(sbuf, ch)                                                        \
  do {                                                                         \
    _Pragma("unroll") for (int i_ = 0; i_ < 4; ++i_) {                         \
      int idx_ = tid + i_ * 256;                                               \
      int r_ = idx_ >> 3, sg_ = idx_ & 7;                                      \
      unsigned sw_ = ((unsigned)(sg_ ^ (r_ & 7))) << 4;                        \
      cpasync16(aA[sbuf] + r_ * 128 + sw_,                                     \
                Asrc + (size_t)r_ * kKS + (ch) * 64 + sg_ * 8);                \
      cpasync16(aB[sbuf] + r_ * 128 + sw_,                                     \
                Bsrc + (size_t)r_ * kKS + (ch) * 64 + sg_ * 8);                \
    }                                                                          \
    asm volatile("cp.async.commit_group;" ::: "memory");                       \
  } while (0)

  STAGE(0, 0);
  for (int ch = 0; ch < kKS / 64; ++ch) {
    const int s = ch & 1;
    if (ch < kKS / 64 - 1) {
      STAGE(s ^ 1, ch + 1);
      asm volatile("cp.async.wait_group 1;" ::: "memory");
    } else {
      asm volatile("cp.async.wait_group 0;" ::: "memory");
    }
    __syncthreads();
#pragma unroll
    for (int ks = 0; ks < 4; ++ks) {
      unsigned af[4][4], bq[2][4];
      const int cs = ks * 2 + (lane >> 4);
#pragma unroll
      for (int mi = 0; mi < 4; ++mi) {
        int row = wm + mi * 16 + (lane & 15);
        ldmx4(af[mi], aA[s] + row * 128 + ((unsigned)(cs ^ (row & 7)) << 4));
      }
#pragma unroll
      for (int nj = 0; nj < 2; ++nj) {
        int row = wn + nj * 16 + (lane & 15);
        ldmx4(bq[nj], aB[s] + row * 128 + ((unsigned)(cs ^ (row & 7)) << 4));
      }
#pragma unroll
      for (int mi = 0; mi < 4; ++mi) {
        mma_bf16(acc[mi][0], af[mi], bq[0][0], bq[0][2]);
        mma_bf16(acc[mi][1], af[mi], bq[0][1], bq[0][3]);
        mma_bf16(acc[mi][2], af[mi], bq[1][0], bq[1][2]);
        mma_bf16(acc[mi][3], af[mi], bq[1][1], bq[1][3]);
      }
    }
    __syncthreads();
  }
#undef STAGE

  const int b = m0 >> 11;
  const int mat = n0 >> 10;
  float* qkvout = (mat == 0 ? g_q : (mat == 1 ? g_k : g_v));
#pragma unroll
  for (int mi = 0; mi < 4; ++mi) {
#pragma unroll
    for (int ni = 0; ni < 4; ++ni) {
      int rl = wm + mi * 16 + (lane >> 2);
      int n = n0 + wn + ni * 8 + (lane & 3) * 2;
      if (mode == 0) {
        int h = (n >> 6) & 15, dk = n & 63;
        size_t rowbase = (size_t)(b * kH + h) * kS + (m0 & (kS - 1));
        *(float2*)&qkvout[(rowbase + rl) * kDK + dk] =
            make_float2(acc[mi][ni][0], acc[mi][ni][1]);
        *(float2*)&qkvout[(rowbase + rl + 8) * kDK + dk] =
            make_float2(acc[mi][ni][2], acc[mi][ni][3]);
        if (mat == 0) {
          __nv_bfloat162 p0, p1;
          p0.x = __float2bfloat16_rn(acc[mi][ni][0] * 0.125f);
          p0.y = __float2bfloat16_rn(acc[mi][ni][1] * 0.125f);
          p1.x = __float2bfloat16_rn(acc[mi][ni][2] * 0.125f);
          p1.y = __float2bfloat16_rn(acc[mi][ni][3] * 0.125f);
          *(__nv_bfloat162*)&g_qh[(rowbase + rl) * kDK + dk] = p0;
          *(__nv_bfloat162*)&g_qh[(rowbase + rl + 8) * kDK + dk] = p1;
        } else if (mat == 1) {
          __nv_bfloat162 p0, p1;
          p0.x = __float2bfloat16_rn(acc[mi][ni][0]);
          p0.y = __float2bfloat16_rn(acc[mi][ni][1]);
          p1.x = __float2bfloat16_rn(acc[mi][ni][2]);
          p1.y = __float2bfloat16_rn(acc[mi][ni][3]);
          *(__nv_bfloat162*)&g_kh[(rowbase + rl) * kDK + dk] = p0;
          *(__nv_bfloat162*)&g_kh[(rowbase + rl + 8) * kDK + dk] = p1;
        }
      } else {
        int m = m0 + rl;
        *(float2*)&outP[(size_t)m * kD + n] =
            make_float2(acc[mi][ni][0], acc[mi][ni][1]);
        *(float2*)&outP[(size_t)(m + 8) * kD + n] =
            make_float2(acc[mi][ni][2], acc[mi][ni][3]);
      }
    }
  }
}

// ---------------------------------------------------------------------------
// attn_smax: S ~= Qhi Khi^T via HMMA; 128 threads = 4 warps x 32 q-rows each
// (K fragments amortized over 2 m16 MMAs). cp.async double-buffered K tiles;
// hierarchical shortlist guard; margin 70.
// smem: Qhi 16K + K0 16K + K1 16K + cnt 512 + slots 8K = 57856 B.
// ---------------------------------------------------------------------------
__global__ __launch_bounds__(128) void attn_smax_kernel() {
  extern __shared__ char sm[];
  const unsigned sb = smem_u32(sm);
  const unsigned aQhi = sb;
  const unsigned aK[2] = {sb + 16384, sb + 32768};
  int* scnt = (int*)(sm + 49152);
  unsigned short* stid = (unsigned short*)(sm + 49664);

  const int tid = threadIdx.x;
  const int warp = tid >> 5, lane = tid & 31;
  const int qt = blockIdx.x, h = blockIdx.y, b = blockIdx.z;
  const int bh = b * kH + h;
  const int wq = warp << 5;  // warp's first q-row (32 rows per warp)

  scnt[tid] = 0;

  const __nv_bfloat16* qsrc = g_qh + ((size_t)bh * kS + qt * 128) * kDK;
#pragma unroll
  for (int it = 0; it < 8; ++it) {
    int idx = tid + it * 128;
    int row = idx >> 3, g = idx & 7;
    unsigned sw = ((unsigned)(g ^ (row & 7))) << 4;
    *(uint4*)(sm + row * 128 + sw) = *(const uint4*)(qsrc + (size_t)row * kDK + g * 8);
  }

  const __nv_bfloat16* ksrc = g_kh + (size_t)bh * kS * kDK;

#define KSTAGE(sbuf, kt)                                                       \
  do {                                                                         \
    _Pragma("unroll") for (int i_ = 0; i_ < 8; ++i_) {                         \
      int idx_ = tid + i_ * 128;                                               \
      int r_ = idx_ >> 3, g_ = idx_ & 7;                                       \
      unsigned sw_ = ((unsigned)(g_ ^ (r_ & 7))) << 4;                         \
      cpasync16(aK[sbuf] + r_ * 128 + sw_,                                     \
                ksrc + ((size_t)(kt) * 128 + r_) * kDK + g_ * 8);              \
    }                                                                          \
    asm volatile("cp.async.commit_group;" ::: "memory");                       \
  } while (0)

  // running maxes: [mi][rowhalf] -> rows wq + mi*16 + (lane>>2) + rowhalf*8
  float m00 = -3.0e38f, m01 = -3.0e38f, m10 = -3.0e38f, m11 = -3.0e38f;
  const int r0 = lane >> 2;
  constexpr int NT = kS / 128;  // 16

  KSTAGE(0, 0);
  for (int kt = 0; kt < NT; ++kt) {
    const int s = kt & 1;
    if (kt < NT - 1) {
      KSTAGE(s ^ 1, kt + 1);
      asm volatile("cp.async.wait_group 1;" ::: "memory");
    } else {
      asm volatile("cp.async.wait_group 0;" ::: "memory");
    }
    __syncthreads();

    float acc[2][16][4];
#pragma unroll
    for (int mi = 0; mi < 2; ++mi)
#pragma unroll
      for (int tt = 0; tt < 16; ++tt)
#pragma unroll
        for (int j = 0; j < 4; ++j) acc[mi][tt][j] = 0.f;

#pragma unroll
    for (int kc = 0; kc < 4; ++kc) {
      unsigned aHi[2][4];
      const int cs = kc * 2 + (lane >> 4);
#pragma unroll
      for (int mi = 0; mi < 2; ++mi) {
        int rowq = wq + mi * 16 + (lane & 15);
        unsigned swq = ((unsigned)(cs ^ (rowq & 7))) << 4;
        ldmx4(aHi[mi], aQhi + rowq * 128 + swq);
      }
#pragma unroll
      for (int t3 = 0; t3 < 8; ++t3) {
        int rowb = t3 * 16 + (lane & 15);
        unsigned swb = ((unsigned)(cs ^ (rowb & 7))) << 4;
        unsigned kb[4];
        ldmx4(kb, aK[s] + rowb * 128 + swb);
#pragma unroll
        for (int mi = 0; mi < 2; ++mi) {
          mma_bf16(acc[mi][t3 * 2], aHi[mi], kb[0], kb[2]);
          mma_bf16(acc[mi][t3 * 2 + 1], aHi[mi], kb[1], kb[3]);
        }
      }
    }

    // update running row maxes
    float l00 = -3.0e38f, l01 = -3.0e38f, l10 = -3.0e38f, l11 = -3.0e38f;
#pragma unroll
    for (int tt = 0; tt < 16; ++tt) {
      l00 = fmaxf(l00, fmaxf(acc[0][tt][0], acc[0][tt][1]));
      l01 = fmaxf(l01, fmaxf(acc[0][tt][2], acc[0][tt][3]));
      l10 = fmaxf(l10, fmaxf(acc[1][tt][0], acc[1][tt][1]));
      l11 = fmaxf(l11, fmaxf(acc[1][tt][2], acc[1][tt][3]));
    }
    l00 = fmaxf(l00, __shfl_xor_sync(0xffffffffu, l00, 1));
    l00 = fmaxf(l00, __shfl_xor_sync(0xffffffffu, l00, 2));
    l01 = fmaxf(l01, __shfl_xor_sync(0xffffffffu, l01, 1));
    l01 = fmaxf(l01, __shfl_xor_sync(0xffffffffu, l01, 2));
    l10 = fmaxf(l10, __shfl_xor_sync(0xffffffffu, l10, 1));
    l10 = fmaxf(l10, __shfl_xor_sync(0xffffffffu, l10, 2));
    l11 = fmaxf(l11, __shfl_xor_sync(0xffffffffu, l11, 1));
    l11 = fmaxf(l11, __shfl_xor_sync(0xffffffffu, l11, 2));
    m00 = fmaxf(m00, l00);
    m01 = fmaxf(m01, l01);
    m10 = fmaxf(m10, l10);
    m11 = fmaxf(m11, l11);

    // hierarchical shortlist guard (exact)
    const float t00 = m00 - 70.f, t01 = m01 - 70.f;
    const float t10 = m10 - 70.f, t11 = m11 - 70.f;
#pragma unroll
    for (int mi = 0; mi < 2; ++mi) {
      const float thA = mi ? t10 : t00;
      const float thB = mi ? t11 : t01;
      const int rA = wq + mi * 16 + r0;
      const int rB = rA + 8;
#pragma unroll
      for (int tt = 0; tt < 16; ++tt) {
        int tb = kt * 128 + tt * 8 + (lane & 3) * 2;
        if (fmaxf(acc[mi][tt][0], acc[mi][tt][1]) > thA) {
          if (acc[mi][tt][0] > thA) {
            int i = atomicAdd(&scnt[rA], 1);
            if (i < kCap) stid[rA * kCap + i] = (unsigned short)tb;
          }
          if (acc[mi][tt][1] > thA) {
            int i = atomicAdd(&scnt[rA], 1);
            if (i < kCap) stid[rA * kCap + i] = (unsigned short)(tb + 1);
          }
        }
        if (fmaxf(acc[mi][tt][2], acc[mi][tt][3]) > thB) {
          if (acc[mi][tt][2] > thB) {
            int i = atomicAdd(&scnt[rB], 1);
            if (i < kCap) stid[rB * kCap + i] = (unsigned short)tb;
          }
          if (acc[mi][tt][3] > thB) {
            int i = atomicAdd(&scnt[rB], 1);
            if (i < kCap) stid[rB * kCap + i] = (unsigned short)(tb + 1);
          }
        }
      }
    }
    __syncthreads();
  }
#undef KSTAGE

  {
    size_t rowg_base = ((size_t)bh * 16 + qt) * 128;
    if ((lane & 3) == 0) {
      g_rowmax[rowg_base + wq + r0] = m00;
      g_rowmax[rowg_base + wq + r0 + 8] = m01;
      g_rowmax[rowg_base + wq + r0 + 16] = m10;
      g_rowmax[rowg_base + wq + r0 + 24] = m11;
    }
  }

  {
    size_t row_g = ((size_t)bh * 16 + qt) * 128 + tid;
    int c = scnt[tid];
    g_cnt[row_g] = c;
    int cc = c < kCap ? c : kCap;
    for (int i = 0; i < cc; ++i) g_slot[row_g * kCap + i] = stid[tid * kCap + i];
  }
}

// ---------------------------------------------------------------------------
// attn_gather: warp per q-row; exact fp32 softmax over shortlist using the
// smax shift; gathers V; writes bf16 [hi|lo|hi] split of attn-out directly.
// ---------------------------------------------------------------------------
__global__ __launch_bounds__(256) void attn_gather_kernel() {
  const int warp = threadIdx.x >> 5, lane = threadIdx.x & 31;
  const size_t row_g = (size_t)blockIdx.x * 8 + warp;
  const int qrow = (int)(row_g & 127);
  const int qt = (int)((row_g >> 7) & 15);
  const int h = (int)((row_g >> 11) & 15);
  const int b = (int)(row_g >> 15);
  const int bh = b * kH + h;
  const int sq = qt * 128 + qrow;

  const float* qp = g_q + ((size_t)bh * kS + sq) * kDK;
  const float* kb = g_k + (size_t)bh * kS * kDK;
  const float* vb = g_v + (size_t)bh * kS * kDK;

  const float q0 = qp[lane] * 0.125f, q1 = qp[lane + 32] * 0.125f;
  const int cnt = g_cnt[row_g];

  float l = 0.f, a0 = 0.f, a1 = 0.f;
  if (cnt <= kCap) {
    const float m = g_rowmax[row_g];
    const unsigned short* sl = g_slot + row_g * kCap;
    for (int i = 0; i < cnt; ++i) {
      int t = sl[i];
      float d = q0 * kb[(size_t)t * kDK + lane] + q1 * kb[(size_t)t * kDK + lane + 32];
#pragma unroll
      for (int o = 16; o > 0; o >>= 1) d += __shfl_xor_sync(0xffffffffu, d, o);
      float p = __expf(d - m);
      l += p;
      a0 += p * vb[(size_t)t * kDK + lane];
      a1 += p * vb[(size_t)t * kDK + lane + 32];
    }
  } else {
    float m = -3.0e38f;
    for (int t = 0; t < kS; ++t) {
      float d = q0 * kb[(size_t)t * kDK + lane] + q1 * kb[(size_t)t * kDK + lane + 32];
#pragma unroll
      for (int o = 16; o > 0; o >>= 1) d += __shfl_xor_sync(0xffffffffu, d, o);
      float v0 = vb[(size_t)t * kDK + lane], v1 = vb[(size_t)t * kDK + lane + 32];
      if (d > m) {
        float c = __expf(m - d);
        m = d;
        l = l * c + 1.f;
        a0 = a0 * c + v0;
        a1 = a1 * c + v1;
      } else {
        float p = __expf(d - m);
        l += p;
        a0 += p * v0;
        a1 += p * v1;
      }
    }
  }
  float inv = 1.f / l;
  float o0 = a0 * inv, o1 = a1 * inv;
  unsigned short h0, l0, h1, l1;
  split1(o0, h0, l0);
  split1(o1, h1, l1);
  __nv_bfloat16* base = g_aos + ((size_t)b * kS + sq) * kKS + h * kDK;
  base[lane] = __ushort_as_bfloat16(h0);
  base[lane + 32] = __ushort_as_bfloat16(h1);
  base[1024 + lane] = __ushort_as_bfloat16(l0);
  base[1024 + lane + 32] = __ushort_as_bfloat16(l1);
  base[2048 + lane] = __ushort_as_bfloat16(h0);
  base[2048 + lane + 32] = __ushort_as_bfloat16(h1);
}

// ---------------------------------------------------------------------------
extern "C" void kernel_launch(void* const* d_in, const int* in_sizes, int n_in,
                              void* d_out, int out_size) {
  (void)in_sizes; (void)n_in; (void)out_size;
  const float* x  = (const float*)d_in[0];
  const float* Wq = (const float*)d_in[1];
  const float* Wk = (const float*)d_in[2];
  const float* Wv = (const float*)d_in[3];
  const float* Wo = (const float*)d_in[4];
  float* out = (float*)d_out;

  static int attr_set = 0;
  if (!attr_set) {
    cudaFuncSetAttribute(mm_bf16_kernel,
                         cudaFuncAttributeMaxDynamicSharedMemorySize, 65536);
    cudaFuncSetAttribute(attn_smax_kernel,
                         cudaFuncAttributeMaxDynamicSharedMemorySize, 57856);
    attr_set = 1;
  }

  __nv_bfloat16* xs;  cudaGetSymbolAddress((void**)&xs, g_xs);
  __nv_bfloat16* ws;  cudaGetSymbolAddress((void**)&ws, g_ws);
  __nv_bfloat16* wos; cudaGetSymbolAddress((void**)&wos, g_wos);
  __nv_bfloat16* aos; cudaGetSymbolAddress((void**)&aos, g_aos);

  split_act_kernel<<<kB * kS, 256>>>(x, xs);
  split_weights_kernel<<<3 * kH * kDK + kD, 256>>>(Wq, Wk, Wv, Wo);
  mm_bf16_kernel<<<dim3(kB * kS / 128, kKS / 128), 256, 65536>>>(xs, ws, nullptr, 0);
  attn_smax_kernel<<<dim3(kS / 128, kH, kB), 128, 57856>>>();
  attn_gather_kernel<<<kB * kH * kS / 8, 256>>>();
  mm_bf16_kernel<<<dim3(kB * kS / 128, kD / 128), 256, 65536>>>(aos, wos, out, 1);
}

// round 17
// speedup vs baseline: 1.0997x; 1.0997x over previous
#include <cuda_runtime.h>
#include <cuda_bf16.h>

constexpr int kB = 4, kS = 2048, kD = 1024, kH = 16, kDK = 64;
constexpr int kKS = 3072;  // logical split-K (48 chunks of 64)
constexpr int kKP = 2048;  // physical panel width [hi | lo]
constexpr int kCap = 32;   // shortlist capacity per row

__device__ __forceinline__ unsigned smem_u32(const void* p) {
  unsigned a;
  asm("{ .reg .u64 t; cvta.to.shared.u64 t, %1; cvt.u32.u64 %0, t; }"
      : "=r"(a) : "l"(p));
  return a;
}

// ---------------- mma.sync helpers (sm_80-class PTX) ----------------
__device__ __forceinline__ void cpasync16(unsigned dst, const void* src) {
  asm volatile("cp.async.cg.shared.global [%0], [%1], 16;" :: "r"(dst), "l"(src));
}
__device__ __forceinline__ void ldmx4(unsigned* r, unsigned addr) {
  asm volatile("ldmatrix.sync.aligned.m8n8.x4.shared.b16 {%0,%1,%2,%3}, [%4];"
               : "=r"(r[0]), "=r"(r[1]), "=r"(r[2]), "=r"(r[3]) : "r"(addr));
}
__device__ __forceinline__ void mma_bf16(float* d, const unsigned* a,
                                         unsigned b0, unsigned b1) {
  asm volatile(
      "mma.sync.aligned.m16n8k16.row.col.f32.bf16.bf16.f32 "
      "{%0,%1,%2,%3}, {%4,%5,%6,%7}, {%8,%9}, {%0,%1,%2,%3};"
      : "+f"(d[0]), "+f"(d[1]), "+f"(d[2]), "+f"(d[3])
      : "r"(a[0]), "r"(a[1]), "r"(a[2]), "r"(a[3]), "r"(b0), "r"(b1));
}

// ---------------- scratch ----------------
__device__ __align__(16) float g_q [(size_t)kB * kH * kS * kDK];
__device__ __align__(16) float g_k [(size_t)kB * kH * kS * kDK];
__device__ __align__(16) float g_v [(size_t)kB * kH * kS * kDK];
__device__ __align__(16) __nv_bfloat16 g_qh[(size_t)kB * kH * kS * kDK];  // bf16(0.125*q)
__device__ __align__(16) __nv_bfloat16 g_kh[(size_t)kB * kH * kS * kDK];  // bf16(k)
__device__ __align__(16) __nv_bfloat16 g_xs [(size_t)kB * kS * kKP];
__device__ __align__(16) __nv_bfloat16 g_ws [(size_t)3 * kH * kDK * kKP];
__device__ __align__(16) __nv_bfloat16 g_wos[(size_t)kD * kKP];
__device__ __align__(16) __nv_bfloat16 g_aos[(size_t)kB * kS * kKP];
__device__ int            g_cnt [(size_t)kB * kH * kS];
__device__ float          g_rowmax[(size_t)kB * kH * kS];
__device__ unsigned short g_slot[(size_t)kB * kH * kS * kCap];

__device__ __forceinline__ void split1(float x, unsigned short& h,
                                       unsigned short& l) {
  __nv_bfloat16 hb = __float2bfloat16_rn(x);
  __nv_bfloat16 lb = __float2bfloat16_rn(x - __bfloat162float(hb));
  h = __bfloat16_as_ushort(hb);
  l = __bfloat16_as_ushort(lb);
}

// ---------------- split kernels ----------------
__global__ __launch_bounds__(256) void split_act_kernel(
    const float* __restrict__ src, __nv_bfloat16* __restrict__ dst) {
  const int m = blockIdx.x;
  const int t = threadIdx.x;
  float4 v = *(const float4*)&src[(size_t)m * kD + t * 4];
  unsigned short h[4], l[4];
  split1(v.x, h[0], l[0]); split1(v.y, h[1], l[1]);
  split1(v.z, h[2], l[2]); split1(v.w, h[3], l[3]);
  uint2 hp = make_uint2((unsigned)h[0] | ((unsigned)h[1] << 16),
                        (unsigned)h[2] | ((unsigned)h[3] << 16));
  uint2 lp = make_uint2((unsigned)l[0] | ((unsigned)l[1] << 16),
                        (unsigned)l[2] | ((unsigned)l[3] << 16));
  __nv_bfloat16* base = dst + (size_t)m * kKP;
  *(uint2*)(base + t * 4) = hp;
  *(uint2*)(base + 1024 + t * 4) = lp;
}

// merged QKV-weight + Wo split: grid 4096 (0..3071 -> g_ws, 3072.. -> g_wos)
__global__ __launch_bounds__(256) void split_weights_kernel(
    const float* __restrict__ Wq, const float* __restrict__ Wk,
    const float* __restrict__ Wv, const float* __restrict__ Wo) {
  const int ng = blockIdx.x;
  const float* src;
  __nv_bfloat16* dst;
  size_t stride;
  if (ng < 3072) {
    const int mat = ng >> 10;
    const int h = (ng >> 6) & 15;
    const int n = ng & 63;
    const float* W = (mat == 0 ? Wq : (mat == 1 ? Wk : Wv));
    src = W + (size_t)h * kD * kDK + n;
    stride = kDK;
    dst = g_ws + (size_t)ng * kKP;
  } else {
    const int n = ng - 3072;
    src = Wo + n;
    stride = kD;
    dst = g_wos + (size_t)n * kKP;
  }
#pragma unroll
  for (int it = 0; it < 4; ++it) {
    int d = threadIdx.x + it * 256;
    unsigned short hh, ll;
    split1(src[(size_t)d * stride], hh, ll);
    dst[d] = __ushort_as_bfloat16(hh);
    dst[1024 + d] = __ushort_as_bfloat16(ll);
  }
}

// ---------------------------------------------------------------------------
// HMMA GEMM (R12-R15 proven core). C[128 x 128] = A * B^T over logical K=3072
// with dedup'd physical panels (A: [xhi|xlo], B: [Whi|Wlo]):
//   chunk ch: aoff = ch<32 ? ch : ch-32 ; boff = ch<16 ? ch : ch-16
// mode 0: QKV (emits fp32 q/k/v + bf16 q-hi (x0.125) and k-hi panels).
// mode 1: proj -> d_out.
// ---------------------------------------------------------------------------
__global__ __launch_bounds__(256) void mm_bf16_kernel(
    const __nv_bfloat16* __restrict__ A, const __nv_bfloat16* __restrict__ Bm,
    float* __restrict__ outP, int mode) {
  extern __shared__ char smem[];
  const unsigned sbase = smem_u32(smem);
  const unsigned aA[2] = {sbase, sbase + 16384};
  const unsigned aB[2] = {sbase + 32768, sbase + 49152};

  const int tid = threadIdx.x;
  const int wid = tid >> 5, lane = tid & 31;
  const int m0 = blockIdx.x * 128, n0 = blockIdx.y * 128;
  const int wm = (wid >> 2) * 64, wn = (wid & 3) * 32;
  const __nv_bfloat16* Asrc = A + (size_t)m0 * kKP;
  const __nv_bfloat16* Bsrc = Bm + (size_t)n0 * kKP;

  float acc[4][4][4];
#pragma unroll
  for (int mi = 0; mi < 4; ++mi)
#pragma unroll
    for (int ni = 0; ni < 4; ++ni)
#pragma unroll
      for (int r = 0; r < 4; ++r) acc[mi][ni][r] = 0.f;

#define STAGE(sbuf, ch)                                                        \
  do {                                                                         \
    const int ach_ = (ch) < 32 ? (ch) : (ch) - 32;                             \
    const int bch_ = (ch) < 16 ? (ch) : (ch) - 16;                             \
    _Pragma("unroll") for (int i_ = 0; i_ < 4; ++i_) {                         \
      int idx_ = tid + i_ * 256;                                               \
      int r_ = idx_ >> 3, sg_ = idx_ & 7;                                      \
      unsigned sw_ = ((unsigned)(sg_ ^ (r_ & 7))) << 4;                        \
      cpasync16(aA[sbuf] + r_ * 128 + sw_,                                     \
                Asrc + (size_t)r_ * kKP + ach_ * 64 + sg_ * 8);                \
      cpasync16(aB[sbuf] + r_ * 128 + sw_,                                     \
                Bsrc + (size_t)r_ * kKP + bch_ * 64 + sg_ * 8);                \
    }                                                                          \
    asm volatile("cp.async.commit_group;" ::: "memory");                       \
  } while (0)

  STAGE(0, 0);
  for (int ch = 0; ch < kKS / 64; ++ch) {
    const int s = ch & 1;
    if (ch < kKS / 64 - 1) {
      STAGE(s ^ 1, ch + 1);
      asm volatile("cp.async.wait_group 1;" ::: "memory");
    } else {
      asm volatile("cp.async.wait_group 0;" ::: "memory");
    }
    __syncthreads();
#pragma unroll
    for (int ks = 0; ks < 4; ++ks) {
      unsigned af[4][4], bq[2][4];
      const int cs = ks * 2 + (lane >> 4);
#pragma unroll
      for (int mi = 0; mi < 4; ++mi) {
        int row = wm + mi * 16 + (lane & 15);
        ldmx4(af[mi], aA[s] + row * 128 + ((unsigned)(cs ^ (row & 7)) << 4));
      }
#pragma unroll
      for (int nj = 0; nj < 2; ++nj) {
        int row = wn + nj * 16 + (lane & 15);
        ldmx4(bq[nj], aB[s] + row * 128 + ((unsigned)(cs ^ (row & 7)) << 4));
      }
#pragma unroll
      for (int mi = 0; mi < 4; ++mi) {
        mma_bf16(acc[mi][0], af[mi], bq[0][0], bq[0][2]);
        mma_bf16(acc[mi][1], af[mi], bq[0][1], bq[0][3]);
        mma_bf16(acc[mi][2], af[mi], bq[1][0], bq[1][2]);
        mma_bf16(acc[mi][3], af[mi], bq[1][1], bq[1][3]);
      }
    }
    __syncthreads();
  }
#undef STAGE

  const int b = m0 >> 11;
  const int mat = n0 >> 10;
  float* qkvout = (mat == 0 ? g_q : (mat == 1 ? g_k : g_v));
#pragma unroll
  for (int mi = 0; mi < 4; ++mi) {
#pragma unroll
    for (int ni = 0; ni < 4; ++ni) {
      int rl = wm + mi * 16 + (lane >> 2);
      int n = n0 + wn + ni * 8 + (lane & 3) * 2;
      if (mode == 0) {
        int h = (n >> 6) & 15, dk = n & 63;
        size_t rowbase = (size_t)(b * kH + h) * kS + (m0 & (kS - 1));
        *(float2*)&qkvout[(rowbase + rl) * kDK + dk] =
            make_float2(acc[mi][ni][0], acc[mi][ni][1]);
        *(float2*)&qkvout[(rowbase + rl + 8) * kDK + dk] =
            make_float2(acc[mi][ni][2], acc[mi][ni][3]);
        if (mat == 0) {
          __nv_bfloat162 p0, p1;
          p0.x = __float2bfloat16_rn(acc[mi][ni][0] * 0.125f);
          p0.y = __float2bfloat16_rn(acc[mi][ni][1] * 0.125f);
          p1.x = __float2bfloat16_rn(acc[mi][ni][2] * 0.125f);
          p1.y = __float2bfloat16_rn(acc[mi][ni][3] * 0.125f);
          *(__nv_bfloat162*)&g_qh[(rowbase + rl) * kDK + dk] = p0;
          *(__nv_bfloat162*)&g_qh[(rowbase + rl + 8) * kDK + dk] = p1;
        } else if (mat == 1) {
          __nv_bfloat162 p0, p1;
          p0.x = __float2bfloat16_rn(acc[mi][ni][0]);
          p0.y = __float2bfloat16_rn(acc[mi][ni][1]);
          p1.x = __float2bfloat16_rn(acc[mi][ni][2]);
          p1.y = __float2bfloat16_rn(acc[mi][ni][3]);
          *(__nv_bfloat162*)&g_kh[(rowbase + rl) * kDK + dk] = p0;
          *(__nv_bfloat162*)&g_kh[(rowbase + rl + 8) * kDK + dk] = p1;
        }
      } else {
        int m = m0 + rl;
        *(float2*)&outP[(size_t)m * kD + n] =
            make_float2(acc[mi][ni][0], acc[mi][ni][1]);
        *(float2*)&outP[(size_t)(m + 8) * kD + n] =
            make_float2(acc[mi][ni][2], acc[mi][ni][3]);
      }
    }
  }
}

// ---------------------------------------------------------------------------
// attn_smax (exact R15 winner): 256 threads = 8 warps x 16 q-rows; pre-split
// bf16 tiles; cp.async double-buffered K tiles; hierarchical guard; margin 70.
// smem: Qhi 16K + K0 16K + K1 16K + cnt 512 + slots 8K = 57856 B.
// ---------------------------------------------------------------------------
__global__ __launch_bounds__(256) void attn_smax_kernel() {
  extern __shared__ char sm[];
  const unsigned sb = smem_u32(sm);
  const unsigned aQhi = sb;
  const unsigned aK[2] = {sb + 16384, sb + 32768};
  int* scnt = (int*)(sm + 49152);
  unsigned short* stid = (unsigned short*)(sm + 49664);

  const int tid = threadIdx.x;
  const int warp = tid >> 5, lane = tid & 31;
  const int qt = blockIdx.x, h = blockIdx.y, b = blockIdx.z;
  const int bh = b * kH + h;

  if (tid < 128) scnt[tid] = 0;

  const __nv_bfloat16* qsrc = g_qh + ((size_t)bh * kS + qt * 128) * kDK;
#pragma unroll
  for (int it = 0; it < 4; ++it) {
    int idx = tid + it * 256;
    int row = idx >> 3, g = idx & 7;
    unsigned sw = ((unsigned)(g ^ (row & 7))) << 4;
    *(uint4*)(sm + row * 128 + sw) = *(const uint4*)(qsrc + (size_t)row * kDK + g * 8);
  }

  const __nv_bfloat16* ksrc = g_kh + (size_t)bh * kS * kDK;

#define KSTAGE(sbuf, kt)                                                       \
  do {                                                                         \
    _Pragma("unroll") for (int i_ = 0; i_ < 4; ++i_) {                         \
      int idx_ = tid + i_ * 256;                                               \
      int r_ = idx_ >> 3, g_ = idx_ & 7;                                       \
      unsigned sw_ = ((unsigned)(g_ ^ (r_ & 7))) << 4;                         \
      cpasync16(aK[sbuf] + r_ * 128 + sw_,                                     \
                ksrc + ((size_t)(kt) * 128 + r_) * kDK + g_ * 8);              \
    }                                                                          \
    asm volatile("cp.async.commit_group;" ::: "memory");                       \
  } while (0)

  float m0 = -3.0e38f, m1 = -3.0e38f;
  const int r0 = (warp << 4) + (lane >> 2);
  constexpr int NT = kS / 128;  // 16

  KSTAGE(0, 0);
  for (int kt = 0; kt < NT; ++kt) {
    const int s = kt & 1;
    if (kt < NT - 1) {
      KSTAGE(s ^ 1, kt + 1);
      asm volatile("cp.async.wait_group 1;" ::: "memory");
    } else {
      asm volatile("cp.async.wait_group 0;" ::: "memory");
    }
    __syncthreads();

    float acc[16][4];
#pragma unroll
    for (int tt = 0; tt < 16; ++tt)
#pragma unroll
      for (int j = 0; j < 4; ++j) acc[tt][j] = 0.f;

#pragma unroll
    for (int kc = 0; kc < 4; ++kc) {
      unsigned aHi[4];
      const int cs = kc * 2 + (lane >> 4);
      int rowq = (warp << 4) + (lane & 15);
      unsigned swq = ((unsigned)(cs ^ (rowq & 7))) << 4;
      ldmx4(aHi, aQhi + rowq * 128 + swq);
#pragma unroll
      for (int t3 = 0; t3 < 8; ++t3) {
        int rowb = t3 * 16 + (lane & 15);
        unsigned swb = ((unsigned)(cs ^ (rowb & 7))) << 4;
        unsigned kb[4];
        ldmx4(kb, aK[s] + rowb * 128 + swb);
        mma_bf16(acc[t3 * 2], aHi, kb[0], kb[2]);
        mma_bf16(acc[t3 * 2 + 1], aHi, kb[1], kb[3]);
      }
    }

    float lm0 = -3.0e38f, lm1 = -3.0e38f;
#pragma unroll
    for (int tt = 0; tt < 16; ++tt) {
      lm0 = fmaxf(lm0, fmaxf(acc[tt][0], acc[tt][1]));
      lm1 = fmaxf(lm1, fmaxf(acc[tt][2], acc[tt][3]));
    }
    lm0 = fmaxf(lm0, __shfl_xor_sync(0xffffffffu, lm0, 1));
    lm0 = fmaxf(lm0, __shfl_xor_sync(0xffffffffu, lm0, 2));
    lm1 = fmaxf(lm1, __shfl_xor_sync(0xffffffffu, lm1, 1));
    lm1 = fmaxf(lm1, __shfl_xor_sync(0xffffffffu, lm1, 2));
    m0 = fmaxf(m0, lm0);
    m1 = fmaxf(m1, lm1);

    float th0 = m0 - 70.f, th1 = m1 - 70.f;
#pragma unroll
    for (int tt = 0; tt < 16; ++tt) {
      int tb = kt * 128 + tt * 8 + (lane & 3) * 2;
      if (fmaxf(acc[tt][0], acc[tt][1]) > th0) {
        if (acc[tt][0] > th0) {
          int i = atomicAdd(&scnt[r0], 1);
          if (i < kCap) stid[r0 * kCap + i] = (unsigned short)tb;
        }
        if (acc[tt][1] > th0) {
          int i = atomicAdd(&scnt[r0], 1);
          if (i < kCap) stid[r0 * kCap + i] = (unsigned short)(tb + 1);
        }
      }
      if (fmaxf(acc[tt][2], acc[tt][3]) > th1) {
        if (acc[tt][2] > th1) {
          int i = atomicAdd(&scnt[r0 + 8], 1);
          if (i < kCap) stid[(r0 + 8) * kCap + i] = (unsigned short)tb;
        }
        if (acc[tt][3] > th1) {
          int i = atomicAdd(&scnt[r0 + 8], 1);
          if (i < kCap) stid[(r0 + 8) * kCap + i] = (unsigned short)(tb + 1);
        }
      }
    }
    __syncthreads();
  }
#undef KSTAGE

  {
    size_t rowg_base = ((size_t)bh * 16 + qt) * 128;
    if ((lane & 3) == 0) {
      g_rowmax[rowg_base + r0] = m0;
      g_rowmax[rowg_base + r0 + 8] = m1;
    }
  }

  if (tid < 128) {
    size_t row_g = ((size_t)bh * 16 + qt) * 128 + tid;
    int c = scnt[tid];
    g_cnt[row_g] = c;
    int cc = c < kCap ? c : kCap;
    for (int i = 0; i < cc; ++i) g_slot[row_g * kCap + i] = stid[tid * kCap + i];
  }
}

// ---------------------------------------------------------------------------
// attn_gather: warp per q-row; exact fp32 softmax over shortlist using the
// smax shift; gathers V; writes bf16 [hi|lo] split of attn-out directly.
// ---------------------------------------------------------------------------
__global__ __launch_bounds__(256) void attn_gather_kernel() {
  const int warp = threadIdx.x >> 5, lane = threadIdx.x & 31;
  const size_t row_g = (size_t)blockIdx.x * 8 + warp;
  const int qrow = (int)(row_g & 127);
  const int qt = (int)((row_g >> 7) & 15);
  const int h = (int)((row_g >> 11) & 15);
  const int b = (int)(row_g >> 15);
  const int bh = b * kH + h;
  const int sq = qt * 128 + qrow;

  const float* qp = g_q + ((size_t)bh * kS + sq) * kDK;
  const float* kb = g_k + (size_t)bh * kS * kDK;
  const float* vb = g_v + (size_t)bh * kS * kDK;

  const float q0 = qp[lane] * 0.125f, q1 = qp[lane + 32] * 0.125f;
  const int cnt = g_cnt[row_g];

  float l = 0.f, a0 = 0.f, a1 = 0.f;
  if (cnt <= kCap) {
    const float m = g_rowmax[row_g];
    const unsigned short* sl = g_slot + row_g * kCap;
    for (int i = 0; i < cnt; ++i) {
      int t = sl[i];
      float d = q0 * kb[(size_t)t * kDK + lane] + q1 * kb[(size_t)t * kDK + lane + 32];
#pragma unroll
      for (int o = 16; o > 0; o >>= 1) d += __shfl_xor_sync(0xffffffffu, d, o);
      float p = __expf(d - m);
      l += p;
      a0 += p * vb[(size_t)t * kDK + lane];
      a1 += p * vb[(size_t)t * kDK + lane + 32];
    }
  } else {
    float m = -3.0e38f;
    for (int t = 0; t < kS; ++t) {
      float d = q0 * kb[(size_t)t * kDK + lane] + q1 * kb[(size_t)t * kDK + lane + 32];
#pragma unroll
      for (int o = 16; o > 0; o >>= 1) d += __shfl_xor_sync(0xffffffffu, d, o);
      float v0 = vb[(size_t)t * kDK + lane], v1 = vb[(size_t)t * kDK + lane + 32];
      if (d > m) {
        float c = __expf(m - d);
        m = d;
        l = l * c + 1.f;
        a0 = a0 * c + v0;
        a1 = a1 * c + v1;
      } else {
        float p = __expf(d - m);
        l += p;
        a0 += p * v0;
        a1 += p * v1;
      }
    }
  }
  float inv = 1.f / l;
  float o0 = a0 * inv, o1 = a1 * inv;
  unsigned short h0, l0, h1, l1;
  split1(o0, h0, l0);
  split1(o1, h1, l1);
  __nv_bfloat16* base = g_aos + ((size_t)b * kS + sq) * kKP + h * kDK;
  base[lane] = __ushort_as_bfloat16(h0);
  base[lane + 32] = __ushort_as_bfloat16(h1);
  base[1024 + lane] = __ushort_as_bfloat16(l0);
  base[1024 + lane + 32] = __ushort_as_bfloat16(l1);
}

// ---------------------------------------------------------------------------
extern "C" void kernel_launch(void* const* d_in, const int* in_sizes, int n_in,
                              void* d_out, int out_size) {
  (void)in_sizes; (void)n_in; (void)out_size;
  const float* x  = (const float*)d_in[0];
  const float* Wq = (const float*)d_in[1];
  const float* Wk = (const float*)d_in[2];
  const float* Wv = (const float*)d_in[3];
  const float* Wo = (const float*)d_in[4];
  float* out = (float*)d_out;

  static int attr_set = 0;
  if (!attr_set) {
    cudaFuncSetAttribute(mm_bf16_kernel,
                         cudaFuncAttributeMaxDynamicSharedMemorySize, 65536);
    cudaFuncSetAttribute(attn_smax_kernel,
                         cudaFuncAttributeMaxDynamicSharedMemorySize, 57856);
    attr_set = 1;
  }

  __nv_bfloat16* xs;  cudaGetSymbolAddress((void**)&xs, g_xs);
  __nv_bfloat16* ws;  cudaGetSymbolAddress((void**)&ws, g_ws);
  __nv_bfloat16* wos; cudaGetSymbolAddress((void**)&wos, g_wos);
  __nv_bfloat16* aos; cudaGetSymbolAddress((void**)&aos, g_aos);

  split_act_kernel<<<kB * kS, 256>>>(x, xs);
  split_weights_kernel<<<3 * kH * kDK + kD, 256>>>(Wq, Wk, Wv, Wo);
  mm_bf16_kernel<<<dim3(kB * kS / 128, kKS / 128), 256, 65536>>>(xs, ws, nullptr, 0);
  attn_smax_kernel<<<dim3(kS / 128, kH, kB), 256, 57856>>>();
  attn_gather_kernel<<<kB * kH * kS / 8, 256>>>();
  mm_bf16_kernel<<<dim3(kB * kS / 128, kD / 128), 256, 65536>>>(aos, wos, out, 1);
}